// round 11
// baseline (speedup 1.0000x reference)
#include <cuda_runtime.h>
#include <cstdint>

#define NB    16384
#define SN    81
#define SS    6561
#define HID   32
#define OBSW  162
#define STAGES 8
#define STAGE_FLOATS 6564          // 26256 B window: 16B-aligned, covers any slice
#define STAGE_BYTES  26256
#define GRID  148
#define TPB   111                  // ceil(16384/148)
#define NTHREADS 160               // warps 0-3 consume, warp 4 produces

// out layout: [0,NB) symbolic | [NB,2NB) imm | [2NB,3NB) next | [3NB,..) nsc BxSN
//
// Resubmit of R10 (container-level infra failure, no kernel verdict).
// Dense-stream design: persistent 148 blocks, dedicated TMA producer warp
// feeding an 8-deep slice ring, 4 consumer warps with static stage ownership.

__device__ __forceinline__ uint32_t s2u(const void* p) {
    uint32_t a;
    asm("{ .reg .u64 t; cvta.to.shared.u64 t, %1; cvt.u32.u64 %0, t; }"
        : "=r"(a) : "l"(p));
    return a;
}
__device__ __forceinline__ void mbar_init(uint32_t a, uint32_t cnt) {
    asm volatile("mbarrier.init.shared.b64 [%0], %1;" :: "r"(a), "r"(cnt) : "memory");
}
__device__ __forceinline__ void mbar_expect_tx(uint32_t a, uint32_t bytes) {
    asm volatile("mbarrier.arrive.expect_tx.shared.b64 _, [%0], %1;"
                 :: "r"(a), "r"(bytes) : "memory");
}
__device__ __forceinline__ void mbar_arrive(uint32_t a) {
    asm volatile("mbarrier.arrive.shared.b64 _, [%0];" :: "r"(a) : "memory");
}
__device__ __forceinline__ void mbar_wait(uint32_t a, uint32_t phase) {
    asm volatile(
        "{\n\t.reg .pred p;\n\t"
        "WAITLOOP_%=:\n\t"
        "mbarrier.try_wait.parity.acquire.cta.shared::cta.b64 p, [%0], %1, 0x989680;\n\t"
        "@!p bra WAITLOOP_%=;\n\t}"
        :: "r"(a), "r"(phase) : "memory");
}
__device__ __forceinline__ void tma_bulk_1d(uint32_t dst, const void* src,
                                            uint32_t bytes, uint32_t mbar) {
    asm volatile(
        "cp.async.bulk.shared::cluster.global.mbarrier::complete_tx::bytes "
        "[%0], [%1], %2, [%3];"
        :: "r"(dst), "l"(src), "r"(bytes), "r"(mbar) : "memory");
}

__global__ __launch_bounds__(NTHREADS, 1) void gdvpn_kernel(
    const float* __restrict__ obs,
    const float* __restrict__ ac,
    const float* __restrict__ W1,
    const float* __restrict__ W2,
    const float* __restrict__ W3,
    const float* __restrict__ b3,
    float* __restrict__ out)
{
    extern __shared__ float sm[];
    const uint32_t smb   = s2u(sm);
    const uint32_t FULL  = smb;        // 8 x 8B
    const uint32_t EMPTY = smb + 64;   // 8 x 8B
    float* buf = sm + 32;              // buffers at byte 128 (16B aligned)
    const uint32_t buf_u = smb + 128;

    const int tid  = threadIdx.x;
    const int w    = tid >> 5;
    const int lane = tid & 31;
    const int start = blockIdx.x * TPB;
    int count = NB - start;
    if (count > TPB) count = TPB;
    if (count < 0)   count = 0;

    if (tid == 0) {
        #pragma unroll
        for (int s = 0; s < STAGES; ++s) {
            mbar_init(FULL + 8 * s, 1);
            mbar_init(EMPTY + 8 * s, 1);
        }
        asm volatile("fence.proxy.async.shared::cta;" ::: "memory");
    }
    __syncthreads();

    if (w == 4) {
        // ---- producer: stream aligned slice windows through the ring ----
        if (lane == 0) {
            int stage = 0, phase = 1;   // fresh-barrier empty-wait passes at parity 1
            for (int i = 0; i < count; ++i) {
                const size_t byte_base = (size_t)(start + i) * (SS * 4);
                const char* src = (const char*)ac + (byte_base & ~(size_t)15);
                mbar_wait(EMPTY + 8 * stage, phase);
                mbar_expect_tx(FULL + 8 * stage, STAGE_BYTES);
                tma_bulk_1d(buf_u + stage * STAGE_BYTES, src, STAGE_BYTES,
                            FULL + 8 * stage);
                if (++stage == STAGES) { stage = 0; phase ^= 1; }
            }
        }
        return;
    }

    // ---- consumers: warp w owns slices i = w, w+4, ... (stages w, w+4) ----
    for (int i = w; i < count; i += 4) {
        const int b     = start + i;
        const int stage = i & 7;
        const int phase = (i >> 3) & 1;

        // prefetch globals that don't depend on the TMA data
        float dem[3];
        #pragma unroll
        for (int k = 0; k < 3; ++k) {
            const int t = lane + 32 * k;
            dem[k] = (t < SN) ? __ldg(obs + (size_t)b * OBSW + SN + t) : 0.0f;
        }

        mbar_wait(FULL + 8 * stage, phase);
        // slice starts (b & 3) floats into its aligned window
        const float* sf = buf + stage * STAGE_FLOATS + (b & 3);

        float v[3];
        float served = 0.0f;
        #pragma unroll
        for (int k = 0; k < 3; ++k) {
            const int t = lane + 32 * k;
            float x = 0.0f;
            if (t < SN) {
                const int c = t % 9;
                const int p = 82 * t;
                x = sf[p];
                if (t >= 9)      x += sf[p - 729];
                if (t < SN - 9)  x += sf[p + 729];
                if (c > 0)       x += sf[p - 81];
                if (c < 8)       x += sf[p + 81];
                served += fminf(x, dem[k]);
            }
            v[k] = x;
        }

        // all smem reads consumed -> release the stage so refill overlaps MLP
        __syncwarp();
        if (lane == 0) mbar_arrive(EMPTY + 8 * stage);

        #pragma unroll
        for (int k = 0; k < 3; ++k) {
            const int t = lane + 32 * k;
            if (t < SN) out[(size_t)3 * NB + (size_t)b * SN + t] = v[k];
        }

        #pragma unroll
        for (int o = 16; o > 0; o >>= 1)
            served += __shfl_down_sync(0xFFFFFFFFu, served, o);
        const float imm = __shfl_sync(0xFFFFFFFFu, served, 0);

        float h1 = 0.0f;
        #pragma unroll
        for (int i2 = 0; i2 < SN; ++i2) {
            const float hm = __shfl_sync(0xFFFFFFFFu, v[i2 >> 5], i2 & 31);
            h1 = fmaf(hm, __ldg(W1 + i2 * HID + lane), h1);
        }
        h1 = fmaxf(h1, 0.0f);

        float h2 = 0.0f;
        #pragma unroll
        for (int m = 0; m < HID; ++m)
            h2 = fmaf(__shfl_sync(0xFFFFFFFFu, h1, m), __ldg(W2 + m * HID + lane), h2);
        h2 = fmaxf(h2, 0.0f);

        float contrib = h2 * __ldg(W3 + lane);
        #pragma unroll
        for (int o = 16; o > 0; o >>= 1)
            contrib += __shfl_down_sync(0xFFFFFFFFu, contrib, o);

        if (lane == 0) {
            const float nr = contrib + __ldg(b3);
            out[b]          = imm + nr;
            out[NB + b]     = imm;
            out[2 * NB + b] = nr;
        }
    }
}

extern "C" void kernel_launch(void* const* d_in, const int* in_sizes, int n_in,
                              void* d_out, int out_size)
{
    const float* obs = (const float*)d_in[0];
    const float* ac  = (const float*)d_in[1];
    const float* W1  = (const float*)d_in[2];
    const float* W2  = (const float*)d_in[3];
    const float* W3  = (const float*)d_in[4];
    const float* b3  = (const float*)d_in[5];
    float* out = (float*)d_out;

    const int smem_bytes = 128 + STAGES * STAGE_BYTES;   // 210,176 B
    cudaFuncSetAttribute(gdvpn_kernel,
                         cudaFuncAttributeMaxDynamicSharedMemorySize, smem_bytes);
    gdvpn_kernel<<<GRID, NTHREADS, smem_bytes>>>(obs, ac, W1, W2, W3, b3, out);
}